// round 11
// baseline (speedup 1.0000x reference)
#include <cuda_runtime.h>
#include <math.h>

#define B_  2
#define S_  2048
#define D_  1024
#define H_  16
#define DH_ 64
#define M_  (B_ * S_)   // 4096

// Scratch (allocation-free rule: __device__ globals)
__device__ float g_Q[B_ * H_ * S_ * DH_];
__device__ float g_K[B_ * H_ * S_ * DH_];
__device__ float g_V[B_ * H_ * S_ * DH_];
__device__ float g_attn[B_ * S_ * D_];

// ---------------------------------------------------------------------------
// GEMM: out[m][n] = sum_k A[m][k] * W[n][k] + bias[n]
// A: [M_, 1024] row-major, W: [1024, 1024] row-major (used transposed)
// scatter=1: write to [B,H,S,Dh] head layout; scatter=0: plain [M_, 1024].
// BM=BN=128, BK=8, 256 threads, 8x8 micro-tile per thread.
// ---------------------------------------------------------------------------
__global__ void __launch_bounds__(256) gemm_bias_kernel(
    const float* __restrict__ A, const float* __restrict__ W,
    const float* __restrict__ bias, float* __restrict__ out, int scatter)
{
    const int K = D_;
    __shared__ float As[8][128];
    __shared__ float Bs[8][128];

    const int bm  = blockIdx.y * 128;
    const int bn  = blockIdx.x * 128;
    const int tid = threadIdx.x;

    const int lrow = tid >> 1;           // 0..127
    const int lcol = (tid & 1) << 2;     // 0 or 4
    const float* Ap = A + (size_t)(bm + lrow) * K + lcol;
    const float* Wp = W + (size_t)(bn + lrow) * K + lcol;

    const int tr = (tid >> 4) << 3;      // 0..120 step 8
    const int tc = (tid & 15) << 3;      // 0..120 step 8

    float acc[8][8];
#pragma unroll
    for (int i = 0; i < 8; i++)
#pragma unroll
        for (int j = 0; j < 8; j++) acc[i][j] = 0.f;

    float4 av = *(const float4*)(Ap);
    float4 wv = *(const float4*)(Wp);

    for (int k0 = 0; k0 < K; k0 += 8) {
        As[lcol + 0][lrow] = av.x; As[lcol + 1][lrow] = av.y;
        As[lcol + 2][lrow] = av.z; As[lcol + 3][lrow] = av.w;
        Bs[lcol + 0][lrow] = wv.x; Bs[lcol + 1][lrow] = wv.y;
        Bs[lcol + 2][lrow] = wv.z; Bs[lcol + 3][lrow] = wv.w;
        __syncthreads();

        if (k0 + 8 < K) {                 // prefetch next tile (hide gmem latency)
            av = *(const float4*)(Ap + k0 + 8);
            wv = *(const float4*)(Wp + k0 + 8);
        }

#pragma unroll
        for (int kk = 0; kk < 8; kk++) {
            float a[8], b[8];
#pragma unroll
            for (int i = 0; i < 8; i++) a[i] = As[kk][tr + i];
#pragma unroll
            for (int j = 0; j < 8; j++) b[j] = Bs[kk][tc + j];
#pragma unroll
            for (int i = 0; i < 8; i++)
#pragma unroll
                for (int j = 0; j < 8; j++)
                    acc[i][j] = fmaf(a[i], b[j], acc[i][j]);
        }
        __syncthreads();
    }

    float bb[8];
#pragma unroll
    for (int j = 0; j < 8; j++) bb[j] = bias[bn + tc + j];

    if (scatter) {
#pragma unroll
        for (int i = 0; i < 8; i++) {
            const int m = bm + tr + i;
            const int b = m >> 11;          // /S_
            const int s = m & (S_ - 1);
#pragma unroll
            for (int j = 0; j < 8; j++) {
                const int n  = bn + tc + j;
                const int h  = n >> 6;
                const int dh = n & 63;
                out[(((size_t)(b * H_ + h)) * S_ + s) * DH_ + dh] = acc[i][j] + bb[j];
            }
        }
    } else {
#pragma unroll
        for (int i = 0; i < 8; i++) {
            const int m = bm + tr + i;
#pragma unroll
            for (int j = 0; j < 8; j++)
                out[(size_t)m * D_ + bn + tc + j] = acc[i][j] + bb[j];
        }
    }
}

// ---------------------------------------------------------------------------
// Flash attention (fp32, causal). One CTA per (b*h, q-tile of 64 rows).
// Smem: Qs[64][64] row-major, KtPs[64][64] = K transposed [d][c], later reused
// as P[r][c]; Vs[64][64] row-major. Exactly 48KB static.
// Thread (rg=tid/16, cg=tid%16) owns rows rg+16i, cols cg+16j (i,j in 0..3).
// ---------------------------------------------------------------------------
__global__ void __launch_bounds__(256) flash_kernel(
    const float* __restrict__ Q, const float* __restrict__ K,
    const float* __restrict__ V, float* __restrict__ O)
{
    __shared__ float Qs[64 * 64];
    __shared__ float KtPs[64 * 64];
    __shared__ float Vs[64 * 64];

    const int bh    = blockIdx.y;                      // b*H + h
    const int qt    = (int)gridDim.x - 1 - (int)blockIdx.x;  // longest CTAs first
    const int qbase = qt * 64;
    const int tid   = threadIdx.x;
    const int rg    = tid >> 4;     // 0..15
    const int cg    = tid & 15;     // 0..15

    const float* Qb = Q + (size_t)bh * S_ * DH_;
    const float* Kb = K + (size_t)bh * S_ * DH_;
    const float* Vb = V + (size_t)bh * S_ * DH_;

    // load Q tile (row-major)
    {
        const int row  = tid >> 2;
        const int col0 = (tid & 3) << 4;
        const float* src = Qb + (size_t)(qbase + row) * DH_ + col0;
#pragma unroll
        for (int u = 0; u < 4; u++) {
            float4 v = *(const float4*)(src + 4 * u);
            float* dst = Qs + row * 64 + col0 + 4 * u;
            dst[0] = v.x; dst[1] = v.y; dst[2] = v.z; dst[3] = v.w;
        }
    }

    float m[4], l[4], o[4][4];
#pragma unroll
    for (int i = 0; i < 4; i++) {
        m[i] = -1e30f; l[i] = 0.f;
#pragma unroll
        for (int j = 0; j < 4; j++) o[i][j] = 0.f;
    }
    __syncthreads();

    for (int kt = 0; kt <= qt; kt++) {
        const int kbase = kt * 64;

        // load K (transposed into KtPs[d][c]) and V (row-major)
        {
            const int row  = tid >> 2;
            const int col0 = (tid & 3) << 4;
            const float* ksrc = Kb + (size_t)(kbase + row) * DH_ + col0;
            const float* vsrc = Vb + (size_t)(kbase + row) * DH_ + col0;
#pragma unroll
            for (int u = 0; u < 4; u++) {
                float4 kv = *(const float4*)(ksrc + 4 * u);
                float4 vv = *(const float4*)(vsrc + 4 * u);
                const int d = col0 + 4 * u;
                KtPs[(d + 0) * 64 + row] = kv.x;
                KtPs[(d + 1) * 64 + row] = kv.y;
                KtPs[(d + 2) * 64 + row] = kv.z;
                KtPs[(d + 3) * 64 + row] = kv.w;
                float* vd = Vs + row * 64 + d;
                vd[0] = vv.x; vd[1] = vv.y; vd[2] = vv.z; vd[3] = vv.w;
            }
        }
        __syncthreads();

        // S = Q K^T (raw dot; scale after)
        float s[4][4];
#pragma unroll
        for (int i = 0; i < 4; i++)
#pragma unroll
            for (int j = 0; j < 4; j++) s[i][j] = 0.f;

#pragma unroll 8
        for (int d = 0; d < 64; d++) {
            float qv[4], kv[4];
#pragma unroll
            for (int i = 0; i < 4; i++) qv[i] = Qs[(rg + 16 * i) * 64 + d];
#pragma unroll
            for (int j = 0; j < 4; j++) kv[j] = KtPs[d * 64 + cg + 16 * j];
#pragma unroll
            for (int i = 0; i < 4; i++)
#pragma unroll
                for (int j = 0; j < 4; j++)
                    s[i][j] = fmaf(qv[i], kv[j], s[i][j]);
        }

        // scale + causal mask (only on the diagonal tile)
        const bool diag = (kt == qt);
#pragma unroll
        for (int i = 0; i < 4; i++)
#pragma unroll
            for (int j = 0; j < 4; j++) {
                s[i][j] *= 0.125f;   // 1/sqrt(64)
                if (diag && (cg + 16 * j) > (rg + 16 * i)) s[i][j] = -1e30f;
            }

        // online softmax (row stats shared by the 16 lanes of each rg group)
        float corr[4];
#pragma unroll
        for (int i = 0; i < 4; i++) {
            float rm = fmaxf(fmaxf(s[i][0], s[i][1]), fmaxf(s[i][2], s[i][3]));
#pragma unroll
            for (int w = 8; w > 0; w >>= 1)
                rm = fmaxf(rm, __shfl_xor_sync(0xffffffffu, rm, w));
            const float mn = fmaxf(m[i], rm);
            corr[i] = __expf(m[i] - mn);
            float rs = 0.f;
#pragma unroll
            for (int j = 0; j < 4; j++) {
                s[i][j] = __expf(s[i][j] - mn);
                rs += s[i][j];
            }
#pragma unroll
            for (int w = 8; w > 0; w >>= 1)
                rs += __shfl_xor_sync(0xffffffffu, rs, w);
            l[i] = l[i] * corr[i] + rs;
            m[i] = mn;
#pragma unroll
            for (int j = 0; j < 4; j++) o[i][j] *= corr[i];
        }

        // all threads done reading Kt before reusing buffer as P
        __syncthreads();
#pragma unroll
        for (int i = 0; i < 4; i++)
#pragma unroll
            for (int j = 0; j < 4; j++)
                KtPs[(rg + 16 * i) * 64 + cg + 16 * j] = s[i][j];
        __syncthreads();

        // O += P @ V
#pragma unroll 8
        for (int c = 0; c < 64; c++) {
            float pv[4], vv[4];
#pragma unroll
            for (int i = 0; i < 4; i++) pv[i] = KtPs[(rg + 16 * i) * 64 + c];
#pragma unroll
            for (int j = 0; j < 4; j++) vv[j] = Vs[c * 64 + cg + 16 * j];
#pragma unroll
            for (int i = 0; i < 4; i++)
#pragma unroll
                for (int j = 0; j < 4; j++)
                    o[i][j] = fmaf(pv[i], vv[j], o[i][j]);
        }
        __syncthreads();
    }

    // epilogue: normalize and write to [B, S, H*Dh]
    const int b = bh >> 4;
    const int h = bh & 15;
#pragma unroll
    for (int i = 0; i < 4; i++) {
        const float inv = 1.f / l[i];
        const int qi = qbase + rg + 16 * i;
#pragma unroll
        for (int j = 0; j < 4; j++) {
            const int dh = cg + 16 * j;
            O[(((size_t)b * S_ + qi) * H_ + h) * DH_ + dh] = o[i][j] * inv;
        }
    }
}

// ---------------------------------------------------------------------------
extern "C" void kernel_launch(void* const* d_in, const int* in_sizes, int n_in,
                              void* d_out, int out_size)
{
    (void)in_sizes; (void)n_in; (void)out_size;
    const float* x   = (const float*)d_in[0];
    const float* W_q = (const float*)d_in[1];
    const float* b_q = (const float*)d_in[2];
    const float* W_k = (const float*)d_in[3];
    const float* b_k = (const float*)d_in[4];
    const float* W_v = (const float*)d_in[5];
    const float* b_v = (const float*)d_in[6];
    const float* W_o = (const float*)d_in[7];
    const float* b_o = (const float*)d_in[8];
    float* out = (float*)d_out;

    float *qp, *kp, *vp, *ap;
    cudaGetSymbolAddress((void**)&qp, g_Q);
    cudaGetSymbolAddress((void**)&kp, g_K);
    cudaGetSymbolAddress((void**)&vp, g_V);
    cudaGetSymbolAddress((void**)&ap, g_attn);

    dim3 ggrid(D_ / 128, M_ / 128);   // (8, 32)
    gemm_bias_kernel<<<ggrid, 256>>>(x, W_q, b_q, qp, 1);
    gemm_bias_kernel<<<ggrid, 256>>>(x, W_k, b_k, kp, 1);
    gemm_bias_kernel<<<ggrid, 256>>>(x, W_v, b_v, vp, 1);

    dim3 fgrid(S_ / 64, B_ * H_);     // (32, 32)
    flash_kernel<<<fgrid, 256>>>(qp, kp, vp, ap);

    gemm_bias_kernel<<<ggrid, 256>>>(ap, W_o, b_o, out, 0);
}

// round 12
// speedup vs baseline: 1.0366x; 1.0366x over previous
#include <cuda_runtime.h>
#include <math.h>

#define B_  2
#define S_  2048
#define D_  1024
#define H_  16
#define DH_ 64
#define M_  (B_ * S_)   // 4096

// Scratch (allocation-free rule: __device__ globals)
__device__ float g_Q[B_ * H_ * S_ * DH_];
__device__ float g_K[B_ * H_ * S_ * DH_];
__device__ float g_V[B_ * H_ * S_ * DH_];
__device__ float g_attn[B_ * S_ * D_];

// ---------------------------------------------------------------------------
// GEMM: out[m][n] = sum_k A[m][k] * W[n][k] + bias[n]   (at fp32 FFMA ceiling)
// ---------------------------------------------------------------------------
__global__ void __launch_bounds__(256) gemm_bias_kernel(
    const float* __restrict__ A, const float* __restrict__ W,
    const float* __restrict__ bias, float* __restrict__ out, int scatter)
{
    const int K = D_;
    __shared__ float As[8][128];
    __shared__ float Bs[8][128];

    const int bm  = blockIdx.y * 128;
    const int bn  = blockIdx.x * 128;
    const int tid = threadIdx.x;

    const int lrow = tid >> 1;
    const int lcol = (tid & 1) << 2;
    const float* Ap = A + (size_t)(bm + lrow) * K + lcol;
    const float* Wp = W + (size_t)(bn + lrow) * K + lcol;

    const int tr = (tid >> 4) << 3;
    const int tc = (tid & 15) << 3;

    float acc[8][8];
#pragma unroll
    for (int i = 0; i < 8; i++)
#pragma unroll
        for (int j = 0; j < 8; j++) acc[i][j] = 0.f;

    float4 av = *(const float4*)(Ap);
    float4 wv = *(const float4*)(Wp);

    for (int k0 = 0; k0 < K; k0 += 8) {
        As[lcol + 0][lrow] = av.x; As[lcol + 1][lrow] = av.y;
        As[lcol + 2][lrow] = av.z; As[lcol + 3][lrow] = av.w;
        Bs[lcol + 0][lrow] = wv.x; Bs[lcol + 1][lrow] = wv.y;
        Bs[lcol + 2][lrow] = wv.z; Bs[lcol + 3][lrow] = wv.w;
        __syncthreads();

        if (k0 + 8 < K) {
            av = *(const float4*)(Ap + k0 + 8);
            wv = *(const float4*)(Wp + k0 + 8);
        }

#pragma unroll
        for (int kk = 0; kk < 8; kk++) {
            float a[8], b[8];
#pragma unroll
            for (int i = 0; i < 8; i++) a[i] = As[kk][tr + i];
#pragma unroll
            for (int j = 0; j < 8; j++) b[j] = Bs[kk][tc + j];
#pragma unroll
            for (int i = 0; i < 8; i++)
#pragma unroll
                for (int j = 0; j < 8; j++)
                    acc[i][j] = fmaf(a[i], b[j], acc[i][j]);
        }
        __syncthreads();
    }

    float bb[8];
#pragma unroll
    for (int j = 0; j < 8; j++) bb[j] = bias[bn + tc + j];

    if (scatter) {
#pragma unroll
        for (int i = 0; i < 8; i++) {
            const int m = bm + tr + i;
            const int b = m >> 11;
            const int s = m & (S_ - 1);
#pragma unroll
            for (int j = 0; j < 8; j++) {
                const int n  = bn + tc + j;
                const int h  = n >> 6;
                const int dh = n & 63;
                out[(((size_t)(b * H_ + h)) * S_ + s) * DH_ + dh] = acc[i][j] + bb[j];
            }
        }
    } else {
#pragma unroll
        for (int i = 0; i < 8; i++) {
            const int m = bm + tr + i;
#pragma unroll
            for (int j = 0; j < 8; j++)
                out[(size_t)m * D_ + bn + tc + j] = acc[i][j] + bb[j];
        }
    }
}

// ---------------------------------------------------------------------------
// Flash attention (fp32, causal), vectorized-LDS version.
// Smem: Qt[d][r] (Q transposed, pre-scaled), KtP (K transposed [d][c],
// later reused as P[r][c] row-major), Vs[c][d] row-major. 48KB static.
// Thread (rg=tid/16, cg=tid%16) owns rows 4rg..4rg+3, cols 4cg..4cg+3.
// QK^T loop: 2x LDS.128 per 16 FMA. PV loop: 1x LDS.128 + 4 broadcast scalars.
// ---------------------------------------------------------------------------
__global__ void __launch_bounds__(256) flash_kernel(
    const float* __restrict__ Q, const float* __restrict__ K,
    const float* __restrict__ V, float* __restrict__ O)
{
    __shared__ float Qt[64 * 64];
    __shared__ float KtP[64 * 64];
    __shared__ float Vs[64 * 64];

    const int bh    = blockIdx.y;
    const int qt    = (int)gridDim.x - 1 - (int)blockIdx.x;  // longest first
    const int qbase = qt * 64;
    const int tid   = threadIdx.x;
    const int rg    = tid >> 4;     // 0..15 -> rows 4rg..4rg+3
    const int cg    = tid & 15;     // 0..15 -> cols 4cg..4cg+3

    const float* Qb = Q + (size_t)bh * S_ * DH_;
    const float* Kb = K + (size_t)bh * S_ * DH_;
    const float* Vb = V + (size_t)bh * S_ * DH_;

    const int row  = tid >> 2;            // 0..63
    const int col0 = (tid & 3) << 4;      // 0,16,32,48

    // load Q transposed into Qt[d][r], folding in the 1/sqrt(64) scale
    {
        const float* src = Qb + (size_t)(qbase + row) * DH_ + col0;
#pragma unroll
        for (int u = 0; u < 4; u++) {
            float4 v = *(const float4*)(src + 4 * u);
            const int d = col0 + 4 * u;
            Qt[(d + 0) * 64 + row] = v.x * 0.125f;
            Qt[(d + 1) * 64 + row] = v.y * 0.125f;
            Qt[(d + 2) * 64 + row] = v.z * 0.125f;
            Qt[(d + 3) * 64 + row] = v.w * 0.125f;
        }
    }

    float m[4], l[4], o[4][4];
#pragma unroll
    for (int i = 0; i < 4; i++) {
        m[i] = -1e30f; l[i] = 0.f;
#pragma unroll
        for (int j = 0; j < 4; j++) o[i][j] = 0.f;
    }
    __syncthreads();

    for (int kt = 0; kt <= qt; kt++) {
        const int kbase = kt * 64;

        // K transposed into KtP[d][c]; V row-major into Vs[c][d]
        {
            const float* ksrc = Kb + (size_t)(kbase + row) * DH_ + col0;
            const float* vsrc = Vb + (size_t)(kbase + row) * DH_ + col0;
#pragma unroll
            for (int u = 0; u < 4; u++) {
                float4 kv = *(const float4*)(ksrc + 4 * u);
                float4 vv = *(const float4*)(vsrc + 4 * u);
                const int d = col0 + 4 * u;
                KtP[(d + 0) * 64 + row] = kv.x;
                KtP[(d + 1) * 64 + row] = kv.y;
                KtP[(d + 2) * 64 + row] = kv.z;
                KtP[(d + 3) * 64 + row] = kv.w;
                *(float4*)(Vs + row * 64 + d) = vv;
            }
        }
        __syncthreads();

        // S = (Q*scale) K^T  — vectorized LDS
        float s[4][4];
#pragma unroll
        for (int i = 0; i < 4; i++)
#pragma unroll
            for (int j = 0; j < 4; j++) s[i][j] = 0.f;

#pragma unroll 8
        for (int d = 0; d < 64; d++) {
            const float4 q4 = *(const float4*)(Qt  + d * 64 + 4 * rg);
            const float4 k4 = *(const float4*)(KtP + d * 64 + 4 * cg);
            const float qv[4] = {q4.x, q4.y, q4.z, q4.w};
            const float kv[4] = {k4.x, k4.y, k4.z, k4.w};
#pragma unroll
            for (int i = 0; i < 4; i++)
#pragma unroll
                for (int j = 0; j < 4; j++)
                    s[i][j] = fmaf(qv[i], kv[j], s[i][j]);
        }

        // causal mask on the diagonal tile only
        if (kt == qt) {
#pragma unroll
            for (int i = 0; i < 4; i++)
#pragma unroll
                for (int j = 0; j < 4; j++)
                    if ((4 * cg + j) > (4 * rg + i)) s[i][j] = -1e30f;
        }

        // online softmax (rows shared across the 16 cg lanes of each rg group)
        float corr[4];
#pragma unroll
        for (int i = 0; i < 4; i++) {
            float rm = fmaxf(fmaxf(s[i][0], s[i][1]), fmaxf(s[i][2], s[i][3]));
#pragma unroll
            for (int w = 8; w > 0; w >>= 1)
                rm = fmaxf(rm, __shfl_xor_sync(0xffffffffu, rm, w));
            const float mn = fmaxf(m[i], rm);
            corr[i] = __expf(m[i] - mn);
            float rs = 0.f;
#pragma unroll
            for (int j = 0; j < 4; j++) {
                s[i][j] = __expf(s[i][j] - mn);
                rs += s[i][j];
            }
#pragma unroll
            for (int w = 8; w > 0; w >>= 1)
                rs += __shfl_xor_sync(0xffffffffu, rs, w);
            l[i] = l[i] * corr[i] + rs;
            m[i] = mn;
#pragma unroll
            for (int j = 0; j < 4; j++) o[i][j] *= corr[i];
        }

        __syncthreads();   // all reads of Kt done before reuse as P

        // store P row-major (float4 per owned row)
#pragma unroll
        for (int i = 0; i < 4; i++)
            *(float4*)(KtP + (4 * rg + i) * 64 + 4 * cg) =
                make_float4(s[i][0], s[i][1], s[i][2], s[i][3]);
        __syncthreads();

        // O += P @ V : pv broadcast scalars, vv LDS.128
#pragma unroll 8
        for (int c = 0; c < 64; c++) {
            float pv[4];
#pragma unroll
            for (int i = 0; i < 4; i++) pv[i] = KtP[(4 * rg + i) * 64 + c];
            const float4 v4 = *(const float4*)(Vs + c * 64 + 4 * cg);
            const float vv[4] = {v4.x, v4.y, v4.z, v4.w};
#pragma unroll
            for (int i = 0; i < 4; i++)
#pragma unroll
                for (int j = 0; j < 4; j++)
                    o[i][j] = fmaf(pv[i], vv[j], o[i][j]);
        }
        __syncthreads();   // done reading P before next tile overwrites KtP
    }

    // epilogue: normalize, write [B, S, H*Dh] with float4 stores
    const int b = bh >> 4;
    const int h = bh & 15;
#pragma unroll
    for (int i = 0; i < 4; i++) {
        const float inv = 1.f / l[i];
        const int qi = qbase + 4 * rg + i;
        float4 ov = make_float4(o[i][0] * inv, o[i][1] * inv,
                                o[i][2] * inv, o[i][3] * inv);
        *(float4*)(O + (((size_t)b * S_ + qi) * H_ + h) * DH_ + 4 * cg) = ov;
    }
}

// ---------------------------------------------------------------------------
extern "C" void kernel_launch(void* const* d_in, const int* in_sizes, int n_in,
                              void* d_out, int out_size)
{
    (void)in_sizes; (void)n_in; (void)out_size;
    const float* x   = (const float*)d_in[0];
    const float* W_q = (const float*)d_in[1];
    const float* b_q = (const float*)d_in[2];
    const float* W_k = (const float*)d_in[3];
    const float* b_k = (const float*)d_in[4];
    const float* W_v = (const float*)d_in[5];
    const float* b_v = (const float*)d_in[6];
    const float* W_o = (const float*)d_in[7];
    const float* b_o = (const float*)d_in[8];
    float* out = (float*)d_out;

    float *qp, *kp, *vp, *ap;
    cudaGetSymbolAddress((void**)&qp, g_Q);
    cudaGetSymbolAddress((void**)&kp, g_K);
    cudaGetSymbolAddress((void**)&vp, g_V);
    cudaGetSymbolAddress((void**)&ap, g_attn);

    dim3 ggrid(D_ / 128, M_ / 128);   // (8, 32)
    gemm_bias_kernel<<<ggrid, 256>>>(x, W_q, b_q, qp, 1);
    gemm_bias_kernel<<<ggrid, 256>>>(x, W_k, b_k, kp, 1);
    gemm_bias_kernel<<<ggrid, 256>>>(x, W_v, b_v, vp, 1);

    dim3 fgrid(S_ / 64, B_ * H_);     // (32, 32)
    flash_kernel<<<fgrid, 256>>>(qp, kp, vp, ap);

    gemm_bias_kernel<<<ggrid, 256>>>(ap, W_o, b_o, out, 0);
}

// round 16
// speedup vs baseline: 1.4902x; 1.4376x over previous
#include <cuda_runtime.h>
#include <cuda_bf16.h>
#include <stdint.h>
#include <math.h>

#define B_  2
#define S_  2048
#define D_  1024
#define H_  16
#define DH_ 64
#define M_  (B_ * S_)   // 4096

// Scratch (allocation-free rule: __device__ globals)
__device__ float g_Q[B_ * H_ * S_ * DH_];
__device__ float g_K[B_ * H_ * S_ * DH_];
__device__ float g_V[B_ * H_ * S_ * DH_];
__device__ float g_attn[B_ * S_ * D_];

// ============================ helpers ======================================
__device__ __forceinline__ uint32_t smem_u32(const void* p) {
    uint32_t a;
    asm("{ .reg .u64 t; cvta.to.shared.u64 t, %1; cvt.u32.u64 %0, t; }"
        : "=r"(a) : "l"(p));
    return a;
}
// pack 2 fp32 -> bf16x2 (lo = a, hi = b)
__device__ __forceinline__ uint32_t pk2(float a, float b) {
    uint32_t r;
    asm("cvt.rn.satfinite.bf16x2.f32 %0, %1, %2;" : "=r"(r) : "f"(b), "f"(a));
    return r;
}
__device__ __forceinline__ float2 unpk2(uint32_t p) {
    __nv_bfloat162 t = *reinterpret_cast<__nv_bfloat162*>(&p);
    return __bfloat1622float2(t);
}
__device__ __forceinline__ void cpa16(uint32_t dst, const void* src) {
    asm volatile("cp.async.ca.shared.global [%0], [%1], 16;"
                 :: "r"(dst), "l"(src));
}
#define CP_COMMIT() asm volatile("cp.async.commit_group;" ::: "memory")
#define CP_WAIT0()  asm volatile("cp.async.wait_group 0;"  ::: "memory")

#define SWZ128(x) ((x) ^ (((x) >> 3) & 0x70))

__device__ __forceinline__ void ldm4(uint32_t* r, uint32_t addr) {
    asm volatile("ldmatrix.sync.aligned.m8n8.x4.shared.b16 {%0,%1,%2,%3}, [%4];"
                 : "=r"(r[0]), "=r"(r[1]), "=r"(r[2]), "=r"(r[3]) : "r"(addr));
}
__device__ __forceinline__ void hmma(float* c, const uint32_t* a,
                                     uint32_t b0, uint32_t b1) {
    asm volatile(
        "mma.sync.aligned.m16n8k16.row.col.f32.bf16.bf16.f32 "
        "{%0,%1,%2,%3}, {%4,%5,%6,%7}, {%8,%9}, {%0,%1,%2,%3};"
        : "+f"(c[0]), "+f"(c[1]), "+f"(c[2]), "+f"(c[3])
        : "r"(a[0]), "r"(a[1]), "r"(a[2]), "r"(a[3]), "r"(b0), "r"(b1));
}

// ===========================================================================
// split-bf16 HMMA GEMM: out[m][n] = sum_k A[m][k]*W[n][k] + bias[n]
// CTA tile 128x128, BK=64, 8 warps (warp tile 32x64), cp.async staging.
// ===========================================================================
#define STG_LD  68                      // floats per staging row (272B, 16B-aligned)
#define STG_SZ  (128 * STG_LD * 4)      // 34816 B per operand per buffer
#define OFF_AH  0
#define OFF_AL  16384
#define OFF_BH  32768
#define OFF_BL  49152
#define OFF_STG 65536
#define GEMM_SMEM (OFF_STG + 4 * STG_SZ)   // 204800 B

__global__ void __launch_bounds__(256) hmma_gemm_kernel(
    const float* __restrict__ A, const float* __restrict__ W,
    const float* __restrict__ bias, float* __restrict__ out, int scatter)
{
    extern __shared__ char smem[];
    const uint32_t sb = smem_u32(smem);
    const int tid  = threadIdx.x;
    const int wid  = tid >> 5;
    const int lane = tid & 31;
    const int bm   = blockIdx.y * 128;
    const int bn   = blockIdx.x * 128;

    const int warp_m = wid & 3;    // 4 warps over M (32 rows each)
    const int warp_n = wid >> 2;   // 2 warps over N (64 cols each)

    float acc[2][8][4];
#pragma unroll
    for (int mf = 0; mf < 2; mf++)
#pragma unroll
        for (int nf = 0; nf < 8; nf++)
#pragma unroll
            for (int v = 0; v < 4; v++) acc[mf][nf][v] = 0.f;

    // ---- cp.async chunk loader ----
    auto load_chunk = [&](int kc, int buf) {
        const float* Ab = A + (size_t)bm * D_ + kc * 64;
        const float* Wb = W + (size_t)bn * D_ + kc * 64;
        const uint32_t sA = sb + OFF_STG + buf * 2 * STG_SZ;
        const uint32_t sBg = sA + STG_SZ;
#pragma unroll
        for (int i = 0; i < 8; i++) {
            const int lin = tid + i * 256;     // 0..2047
            const int row = lin >> 4;          // 0..127
            const int seg = lin & 15;          // 16B segment
            cpa16(sA  + row * 272 + seg * 16, Ab + (size_t)row * D_ + seg * 4);
            cpa16(sBg + row * 272 + seg * 16, Wb + (size_t)row * D_ + seg * 4);
        }
        CP_COMMIT();
    };

    load_chunk(0, 0);

    const int krow  = tid >> 1;          // 0..127
    const int kcol0 = (tid & 1) * 32;    // 0 / 32

    // ldmatrix lane address components
    const int a_r = (lane & 7) + ((lane >> 3) & 1) * 8;   // row within 16
    const int a_c = (lane >> 4) * 8;                      // k sub-offset
    const int b_r = (lane & 7) + (lane >> 4) * 8;         // n row within 16
    const int b_c = ((lane >> 3) & 1) * 8;                // k sub-offset

    for (int kc = 0; kc < 16; kc++) {
        const int buf = kc & 1;
        CP_WAIT0();
        __syncthreads();
        if (kc + 1 < 16) load_chunk(kc + 1, buf ^ 1);

        // ---- convert fp32 staging -> hi/lo bf16 tiles (SW128) ----
        {
            const float* stA = (const float*)(smem + OFF_STG + buf * 2 * STG_SZ)
                               + krow * STG_LD + kcol0;
            const float* stB = (const float*)(smem + OFF_STG + buf * 2 * STG_SZ + STG_SZ)
                               + krow * STG_LD + kcol0;
#pragma unroll
            for (int g = 0; g < 4; g++) {
                const uint32_t off = SWZ128((uint32_t)(krow * 128 + (kcol0 + 8 * g) * 2));
                // A
                float4 f0 = *(const float4*)(stA + 8 * g);
                float4 f1 = *(const float4*)(stA + 8 * g + 4);
                uint4 hi, lo;
                hi.x = pk2(f0.x, f0.y); hi.y = pk2(f0.z, f0.w);
                hi.z = pk2(f1.x, f1.y); hi.w = pk2(f1.z, f1.w);
                {
                    float2 h0 = unpk2(hi.x), h1 = unpk2(hi.y),
                           h2 = unpk2(hi.z), h3 = unpk2(hi.w);
                    lo.x = pk2(f0.x - h0.x, f0.y - h0.y);
                    lo.y = pk2(f0.z - h1.x, f0.w - h1.y);
                    lo.z = pk2(f1.x - h2.x, f1.y - h2.y);
                    lo.w = pk2(f1.z - h3.x, f1.w - h3.y);
                }
                *(uint4*)(smem + OFF_AH + off) = hi;
                *(uint4*)(smem + OFF_AL + off) = lo;
                // B
                f0 = *(const float4*)(stB + 8 * g);
                f1 = *(const float4*)(stB + 8 * g + 4);
                hi.x = pk2(f0.x, f0.y); hi.y = pk2(f0.z, f0.w);
                hi.z = pk2(f1.x, f1.y); hi.w = pk2(f1.z, f1.w);
                {
                    float2 h0 = unpk2(hi.x), h1 = unpk2(hi.y),
                           h2 = unpk2(hi.z), h3 = unpk2(hi.w);
                    lo.x = pk2(f0.x - h0.x, f0.y - h0.y);
                    lo.y = pk2(f0.z - h1.x, f0.w - h1.y);
                    lo.z = pk2(f1.x - h2.x, f1.y - h2.y);
                    lo.w = pk2(f1.z - h3.x, f1.w - h3.y);
                }
                *(uint4*)(smem + OFF_BH + off) = hi;
                *(uint4*)(smem + OFF_BL + off) = lo;
            }
        }
        __syncthreads();

        // ---- MMA over 4 k16-steps, 3 split terms ----
#pragma unroll
        for (int ks = 0; ks < 4; ks++) {
            uint32_t ah[2][4], al[2][4];
#pragma unroll
            for (int mf = 0; mf < 2; mf++) {
                const uint32_t ro = (uint32_t)((warp_m * 32 + mf * 16 + a_r) * 128
                                               + (ks * 16 + a_c) * 2);
                ldm4(ah[mf], sb + OFF_AH + SWZ128(ro));
                ldm4(al[mf], sb + OFF_AL + SWZ128(ro));
            }
#pragma unroll
            for (int nh = 0; nh < 2; nh++) {
                uint32_t bh[2][4], bl[2][4];
#pragma unroll
                for (int p = 0; p < 2; p++) {
                    const uint32_t ro = (uint32_t)((warp_n * 64 + nh * 32 + p * 16 + b_r) * 128
                                                   + (ks * 16 + b_c) * 2);
                    ldm4(bh[p], sb + OFF_BH + SWZ128(ro));
                    ldm4(bl[p], sb + OFF_BL + SWZ128(ro));
                }
#pragma unroll
                for (int mf = 0; mf < 2; mf++)
#pragma unroll
                    for (int p = 0; p < 2; p++) {
                        const int nf = nh * 4 + p * 2;
                        hmma(acc[mf][nf],     ah[mf], bh[p][0], bh[p][1]);
                        hmma(acc[mf][nf],     ah[mf], bl[p][0], bl[p][1]);
                        hmma(acc[mf][nf],     al[mf], bh[p][0], bh[p][1]);
                        hmma(acc[mf][nf + 1], ah[mf], bh[p][2], bh[p][3]);
                        hmma(acc[mf][nf + 1], ah[mf], bl[p][2], bl[p][3]);
                        hmma(acc[mf][nf + 1], al[mf], bh[p][2], bh[p][3]);
                    }
            }
        }
        __syncthreads();   // protect bf16 tiles before next convert
    }

    // ---- epilogue: registers -> gmem (32B-sector coalesced float2) ----
    const int qrow = lane >> 2;          // 0..7
    const int qcol = (lane & 3) * 2;     // 0,2,4,6
#pragma unroll
    for (int mf = 0; mf < 2; mf++) {
#pragma unroll
        for (int nf = 0; nf < 8; nf++) {
            const int n = bn + warp_n * 64 + nf * 8 + qcol;
            const float2 bb = *(const float2*)(bias + n);
#pragma unroll
            for (int half = 0; half < 2; half++) {
                const int m = bm + warp_m * 32 + mf * 16 + qrow + half * 8;
                float2 v = make_float2(acc[mf][nf][2 * half]     + bb.x,
                                       acc[mf][nf][2 * half + 1] + bb.y);
                if (scatter) {
                    const int b = m >> 11, s = m & (S_ - 1);
                    const int h = n >> 6,  dh = n & 63;
                    *(float2*)(out + (((size_t)(b * H_ + h)) * S_ + s) * DH_ + dh) = v;
                } else {
                    *(float2*)(out + (size_t)m * D_ + n) = v;
                }
            }
        }
    }
}

// ---------------------------------------------------------------------------
// Flash attention (fp32, causal) — unchanged (642us).
// ---------------------------------------------------------------------------
__global__ void __launch_bounds__(256) flash_kernel(
    const float* __restrict__ Q, const float* __restrict__ K,
    const float* __restrict__ V, float* __restrict__ O)
{
    __shared__ float Qt[64 * 64];
    __shared__ float KtP[64 * 64];
    __shared__ float Vs[64 * 64];

    const int bh    = blockIdx.y;
    const int qt    = (int)gridDim.x - 1 - (int)blockIdx.x;
    const int qbase = qt * 64;
    const int tid   = threadIdx.x;
    const int rg    = tid >> 4;
    const int cg    = tid & 15;

    const float* Qb = Q + (size_t)bh * S_ * DH_;
    const float* Kb = K + (size_t)bh * S_ * DH_;
    const float* Vb = V + (size_t)bh * S_ * DH_;

    const int row  = tid >> 2;
    const int col0 = (tid & 3) << 4;

    {
        const float* src = Qb + (size_t)(qbase + row) * DH_ + col0;
#pragma unroll
        for (int u = 0; u < 4; u++) {
            float4 v = *(const float4*)(src + 4 * u);
            const int d = col0 + 4 * u;
            Qt[(d + 0) * 64 + row] = v.x * 0.125f;
            Qt[(d + 1) * 64 + row] = v.y * 0.125f;
            Qt[(d + 2) * 64 + row] = v.z * 0.125f;
            Qt[(d + 3) * 64 + row] = v.w * 0.125f;
        }
    }

    float m[4], l[4], o[4][4];
#pragma unroll
    for (int i = 0; i < 4; i++) {
        m[i] = -1e30f; l[i] = 0.f;
#pragma unroll
        for (int j = 0; j < 4; j++) o[i][j] = 0.f;
    }
    __syncthreads();

    for (int kt = 0; kt <= qt; kt++) {
        const int kbase = kt * 64;
        {
            const float* ksrc = Kb + (size_t)(kbase + row) * DH_ + col0;
            const float* vsrc = Vb + (size_t)(kbase + row) * DH_ + col0;
#pragma unroll
            for (int u = 0; u < 4; u++) {
                float4 kv = *(const float4*)(ksrc + 4 * u);
                float4 vv = *(const float4*)(vsrc + 4 * u);
                const int d = col0 + 4 * u;
                KtP[(d + 0) * 64 + row] = kv.x;
                KtP[(d + 1) * 64 + row] = kv.y;
                KtP[(d + 2) * 64 + row] = kv.z;
                KtP[(d + 3) * 64 + row] = kv.w;
                *(float4*)(Vs + row * 64 + d) = vv;
            }
        }
        __syncthreads();

        float s[4][4];
#pragma unroll
        for (int i = 0; i < 4; i++)
#pragma unroll
            for (int j = 0; j < 4; j++) s[i][j] = 0.f;

#pragma unroll 8
        for (int d = 0; d < 64; d++) {
            const float4 q4 = *(const float4*)(Qt  + d * 64 + 4 * rg);
            const float4 k4 = *(const float4*)(KtP + d * 64 + 4 * cg);
            const float qv[4] = {q4.x, q4.y, q4.z, q4.w};
            const float kv[4] = {k4.x, k4.y, k4.z, k4.w};
#pragma unroll
            for (int i = 0; i < 4; i++)
#pragma unroll
                for (int j = 0; j < 4; j++)
                    s[i][j] = fmaf(qv[i], kv[j], s[i][j]);
        }

        if (kt == qt) {
#pragma unroll
            for (int i = 0; i < 4; i++)
#pragma unroll
                for (int j = 0; j < 4; j++)
                    if ((4 * cg + j) > (4 * rg + i)) s[i][j] = -1e30f;
        }

        float corr[4];
#pragma unroll
        for (int i = 0; i < 4; i++) {
            float rm = fmaxf(fmaxf(s[i][0], s[i][1]), fmaxf(s[i][2], s[i][3]));
#pragma unroll
            for (int w = 8; w > 0; w >>= 1)
                rm = fmaxf(rm, __shfl_xor_sync(0xffffffffu, rm, w));
            const float mn = fmaxf(m[i], rm);
            corr[i] = __expf(m[i] - mn);
            float rs = 0.f;
#pragma unroll
            for (int j = 0; j < 4; j++) {
                s[i][j] = __expf(s[i][j] - mn);
                rs += s[i][j];
            }
#pragma unroll
            for (int w = 8; w > 0; w >>= 1)
                rs += __shfl_xor_sync(0xffffffffu, rs, w);
            l[i] = l[i] * corr[i] + rs;
            m[i] = mn;
#pragma unroll
            for (int j = 0; j < 4; j++) o[i][j] *= corr[i];
        }

        __syncthreads();
#pragma unroll
        for (int i = 0; i < 4; i++)
            *(float4*)(KtP + (4 * rg + i) * 64 + 4 * cg) =
                make_float4(s[i][0], s[i][1], s[i][2], s[i][3]);
        __syncthreads();

#pragma unroll 8
        for (int c = 0; c < 64; c++) {
            float pv[4];
#pragma unroll
            for (int i = 0; i < 4; i++) pv[i] = KtP[(4 * rg + i) * 64 + c];
            const float4 v4 = *(const float4*)(Vs + c * 64 + 4 * cg);
            const float vv[4] = {v4.x, v4.y, v4.z, v4.w};
#pragma unroll
            for (int i = 0; i < 4; i++)
#pragma unroll
                for (int j = 0; j < 4; j++)
                    o[i][j] = fmaf(pv[i], vv[j], o[i][j]);
        }
        __syncthreads();
    }

    const int b = bh >> 4;
    const int h = bh & 15;
#pragma unroll
    for (int i = 0; i < 4; i++) {
        const float inv = 1.f / l[i];
        const int qi = qbase + 4 * rg + i;
        float4 ov = make_float4(o[i][0] * inv, o[i][1] * inv,
                                o[i][2] * inv, o[i][3] * inv);
        *(float4*)(O + (((size_t)b * S_ + qi) * H_ + h) * DH_ + 4 * cg) = ov;
    }
}

// ---------------------------------------------------------------------------
extern "C" void kernel_launch(void* const* d_in, const int* in_sizes, int n_in,
                              void* d_out, int out_size)
{
    (void)in_sizes; (void)n_in; (void)out_size;
    const float* x   = (const float*)d_in[0];
    const float* W_q = (const float*)d_in[1];
    const float* b_q = (const float*)d_in[2];
    const float* W_k = (const float*)d_in[3];
    const float* b_k = (const float*)d_in[4];
    const float* W_v = (const float*)d_in[5];
    const float* b_v = (const float*)d_in[6];
    const float* W_o = (const float*)d_in[7];
    const float* b_o = (const float*)d_in[8];
    float* out = (float*)d_out;

    float *qp, *kp, *vp, *ap;
    cudaGetSymbolAddress((void**)&qp, g_Q);
    cudaGetSymbolAddress((void**)&kp, g_K);
    cudaGetSymbolAddress((void**)&vp, g_V);
    cudaGetSymbolAddress((void**)&ap, g_attn);

    cudaFuncSetAttribute(hmma_gemm_kernel,
                         cudaFuncAttributeMaxDynamicSharedMemorySize, GEMM_SMEM);

    dim3 ggrid(D_ / 128, M_ / 128);   // (8, 32)
    hmma_gemm_kernel<<<ggrid, 256, GEMM_SMEM>>>(x, W_q, b_q, qp, 1);
    hmma_gemm_kernel<<<ggrid, 256, GEMM_SMEM>>>(x, W_k, b_k, kp, 1);
    hmma_gemm_kernel<<<ggrid, 256, GEMM_SMEM>>>(x, W_v, b_v, vp, 1);

    dim3 fgrid(S_ / 64, B_ * H_);     // (32, 32)
    flash_kernel<<<fgrid, 256>>>(qp, kp, vp, ap);

    hmma_gemm_kernel<<<ggrid, 256, GEMM_SMEM>>>(ap, W_o, b_o, out, 0);
}